// round 15
// baseline (speedup 1.0000x reference)
#include <cuda_runtime.h>
#include <cuda_fp16.h>
#include <mma.h>
#include <math.h>

using namespace nvcuda;

#define NMAX 100000
#define EMAX 1600000
#define NPAD (NMAX + 128)

// ---------------- device scratch ----------------
__device__ float  g_dinv[NMAX];
__device__ int    g_cnt[NMAX];
__device__ int    g_fill[NMAX];
__device__ int    g_rowptr[NMAX + 1];
__device__ int    g_bsum[256];
__device__ int    g_col[EMAX];
// int8 message buffer: row = D int8 + (D/8) half scales, stride D+32 (<=160)
__device__ unsigned char g_q[(size_t)NPAD * 160];
// half activation buffers
__device__ __half g_hB[(size_t)NPAD * 128];   // feature agg out
__device__ __half g_hH2[(size_t)NPAD * 128];  // feature final
__device__ __half g_hD[(size_t)NPAD * 64];    // label agg out
// preconverted fp16 weights: Wg1 | Wg2 | Wl(10) | Wf
__device__ __half g_W[86016];

// ---------------- init: zero counts + convert weights --------------
__global__ void init_kernel(const float* __restrict__ Wg1,
                            const float* __restrict__ Wg2,
                            const float* __restrict__ Wl,
                            const float* __restrict__ Wf, int n) {
    int i = blockIdx.x * blockDim.x + threadIdx.x;
    if (i < n) { g_cnt[i] = 0; g_fill[i] = 0; }
    if (i < 21504) {
        int base = i * 4;
        const float* src;
        int off;
        if (base < 16384)      { src = Wg1; off = base; }
        else if (base < 32768) { src = Wg2; off = base - 16384; }
        else if (base < 73728) { src = Wl;  off = base - 32768; }
        else                   { src = Wf;  off = base - 73728; }
        float4 v = *(const float4*)(src + off);
        uint2 pk;
        __half2* h = (__half2*)&pk;
        h[0] = __floats2half2_rn(v.x, v.y);
        h[1] = __floats2half2_rn(v.z, v.w);
        *(uint2*)&g_W[base] = pk;
    }
}

// ---------------- CSR build ----------------
__global__ void count_edges_kernel(const int* __restrict__ dst, int e) {
    int i = blockIdx.x * blockDim.x + threadIdx.x;
    if (i < e) atomicAdd(&g_cnt[dst[i]], 1);
}

__global__ void scan1_kernel(int n) {
    __shared__ int s[1024];
    int tid = threadIdx.x;
    int i = blockIdx.x * 1024 + tid;
    int v = (i < n) ? g_cnt[i] : 0;
    s[tid] = v;
    __syncthreads();
    for (int off = 1; off < 1024; off <<= 1) {
        int t2 = (tid >= off) ? s[tid - off] : 0;
        __syncthreads();
        s[tid] += t2;
        __syncthreads();
    }
    if (i < n) {
        g_rowptr[i] = s[tid] - v;
        g_dinv[i] = rsqrtf((float)(v + 1));
    }
    if (tid == 1023) g_bsum[blockIdx.x] = s[1023];
}

__global__ void scan2_kernel(int nb) {
    __shared__ int s[128];
    int tid = threadIdx.x;
    int v = (tid < nb) ? g_bsum[tid] : 0;
    s[tid] = v;
    __syncthreads();
    for (int off = 1; off < 128; off <<= 1) {
        int t2 = (tid >= off) ? s[tid - off] : 0;
        __syncthreads();
        s[tid] += t2;
        __syncthreads();
    }
    if (tid < nb) g_bsum[tid] = s[tid] - v;
    if (tid == 127) g_bsum[nb] = s[127];
}

__global__ void scan3_kernel(int n, int nb) {
    int i = blockIdx.x * blockDim.x + threadIdx.x;
    if (i < n) g_rowptr[i] += g_bsum[i >> 10];
    if (i == 0) g_rowptr[n] = g_bsum[nb];
}

__global__ void scatter_edges_kernel(const int* __restrict__ src,
                                     const int* __restrict__ dst, int e) {
    int i = blockIdx.x * blockDim.x + threadIdx.x;
    if (i < e) {
        int d = dst[i];
        int p = g_rowptr[d] + atomicAdd(&g_fill[d], 1);
        g_col[p] = src[i];
    }
}

// ---------------- wmma GEMM ----------------
// EPI 0: half accum -> smem staging -> int8+chunk-scale quantized output
// EPI 1: fp32 accum -> smem staging -> sigmoid, fp32 out
#define GBM 128
#define GBN 64

template <int K, int C, int K1, int EPI, typename TA>
__global__ __launch_bounds__(128) void gemm_wmma_kernel(
    const TA* __restrict__ A1, const __half* __restrict__ A2,
    const __half* __restrict__ Wh, const float* __restrict__ bias,
    void* __restrict__ outv, int n) {
    constexpr int LDW = GBN + 8;   // halves
    constexpr int LDA = K + 8;     // halves
    constexpr int LDSH = GBN + 8;  // halves (EPI=0 staging)
    constexpr int LDS_ = GBN + 4;  // floats (EPI=1 staging)
    constexpr int SB = C + 32;     // int8 row stride (EPI=0)
    extern __shared__ char smraw[];
    __half* Ws = (__half*)smraw;
    __half* As = (__half*)(smraw + (size_t)K * LDW * 2);
    float*  St = (float*)(smraw + (size_t)K * LDW * 2);
    __half* Sh = (__half*)smraw;   // EPI=0 staging aliases whole smem

    const int t = threadIdx.x;
    const int w = t >> 5;
    const int row0 = blockIdx.x * GBM;
    const int bn0 = blockIdx.y * GBN;

    for (int idx = t; idx < K * GBN / 8; idx += 128) {
        int k = idx / (GBN / 8);
        int j = (idx % (GBN / 8)) * 8;
        *(uint4*)&Ws[k * LDW + j] =
            *(const uint4*)(Wh + (size_t)k * C + bn0 + j);
    }

    constexpr int CPR = K / 8;
#pragma unroll
    for (int it = 0; it < GBM * CPR / 128; it++) {
        int cidx = t + it * 128;
        int r = cidx / CPR;
        int kq = (cidx % CPR) * 8;
        int gr = row0 + r;
        uint4 pk = make_uint4(0, 0, 0, 0);
        if (gr < n) {
            float s = (EPI == 0) ? g_dinv[gr] : 1.0f;
            __half2 s2 = __float2half2_rn(s);
            if (kq < K1) {
                if (sizeof(TA) == 2) {
                    uint4 raw = *(const uint4*)((const __half*)A1 +
                                                (size_t)gr * K1 + kq);
                    __half2* h = (__half2*)&raw;
                    if (EPI == 0) {
#pragma unroll
                        for (int q = 0; q < 4; q++) h[q] = __hmul2(h[q], s2);
                    }
                    pk = raw;
                } else {
                    const float* p = (const float*)A1 + (size_t)gr * K1 + kq;
                    float4 a = *(const float4*)p;
                    float4 b = *(const float4*)(p + 4);
                    __half2* h = (__half2*)&pk;
                    h[0] = __floats2half2_rn(s * a.x, s * a.y);
                    h[1] = __floats2half2_rn(s * a.z, s * a.w);
                    h[2] = __floats2half2_rn(s * b.x, s * b.y);
                    h[3] = __floats2half2_rn(s * b.z, s * b.w);
                }
            } else {
                uint4 raw = *(const uint4*)(A2 + (size_t)gr * (K - K1) +
                                            (kq - K1));
                __half2* h = (__half2*)&raw;
                if (EPI == 0) {
#pragma unroll
                    for (int q = 0; q < 4; q++) h[q] = __hmul2(h[q], s2);
                }
                pk = raw;
            }
        }
        *(uint4*)&As[r * LDA + kq] = pk;
    }
    __syncthreads();

    if (EPI == 0) {
        wmma::fragment<wmma::accumulator, 16, 16, 16, __half> acc[2][4];
#pragma unroll
        for (int i = 0; i < 2; i++)
#pragma unroll
            for (int j = 0; j < 4; j++)
                wmma::fill_fragment(acc[i][j], __float2half(0.f));
        for (int k = 0; k < K; k += 16) {
            wmma::fragment<wmma::matrix_a, 16, 16, 16, __half, wmma::row_major> af[2];
            wmma::fragment<wmma::matrix_b, 16, 16, 16, __half, wmma::row_major> bfr[4];
            wmma::load_matrix_sync(af[0], As + (w * 32 + 0) * LDA + k, LDA);
            wmma::load_matrix_sync(af[1], As + (w * 32 + 16) * LDA + k, LDA);
#pragma unroll
            for (int j = 0; j < 4; j++)
                wmma::load_matrix_sync(bfr[j], Ws + k * LDW + j * 16, LDW);
#pragma unroll
            for (int i = 0; i < 2; i++)
#pragma unroll
                for (int j = 0; j < 4; j++)
                    wmma::mma_sync(acc[i][j], af[i], bfr[j], acc[i][j]);
        }
        __syncthreads();  // done with As/Ws; stage into aliased smem
#pragma unroll
        for (int i = 0; i < 2; i++)
#pragma unroll
            for (int j = 0; j < 4; j++)
                wmma::store_matrix_sync(Sh + (w * 32 + i * 16) * LDSH + j * 16,
                                        acc[i][j], LDSH, wmma::mem_row_major);
        __syncthreads();

        // quantize: 128 rows x 8 chunks; each thread 8 chunks
        unsigned char* qo = (unsigned char*)outv;
#pragma unroll
        for (int p = 0; p < 8; p++) {
            int idx = t + p * 128;
            int r = idx >> 3;
            int j = idx & 7;
            int gr = row0 + r;
            if (gr >= n) continue;
            uint4 hv = *(uint4*)&Sh[r * LDSH + j * 8];
            __half2* h = (__half2*)&hv;
            __half2 m2 = __hmax2(__hmax2(__habs2(h[0]), __habs2(h[1])),
                                 __hmax2(__habs2(h[2]), __habs2(h[3])));
            float fm = fmaxf(__half2float(__low2half(m2)),
                             __half2float(__high2half(m2)));
            float inv = (fm > 0.f) ? 127.f / fm : 0.f;
            unsigned int w0 = 0, w1 = 0;
#pragma unroll
            for (int q = 0; q < 2; q++) {
                float2 fa = __half22float2(h[2 * q]);
                float2 fb = __half22float2(h[2 * q + 1]);
                int b0 = __float2int_rn(fa.x * inv) & 255;
                int b1 = __float2int_rn(fa.y * inv) & 255;
                int b2 = __float2int_rn(fb.x * inv) & 255;
                int b3 = __float2int_rn(fb.y * inv) & 255;
                unsigned int wv = b0 | (b1 << 8) | (b2 << 16) | (b3 << 24);
                if (q == 0) w0 = wv; else w1 = wv;
            }
            *(uint2*)(qo + (size_t)gr * SB + bn0 + j * 8) = make_uint2(w0, w1);
            *(__half*)(qo + (size_t)gr * SB + C + ((bn0 >> 3) + j) * 2) =
                __float2half(fm * (1.f / 127.f));
        }
    } else {
        wmma::fragment<wmma::accumulator, 16, 16, 16, float> acc[2][4];
#pragma unroll
        for (int i = 0; i < 2; i++)
#pragma unroll
            for (int j = 0; j < 4; j++) wmma::fill_fragment(acc[i][j], 0.f);
        for (int k = 0; k < K; k += 16) {
            wmma::fragment<wmma::matrix_a, 16, 16, 16, __half, wmma::row_major> af[2];
            wmma::fragment<wmma::matrix_b, 16, 16, 16, __half, wmma::row_major> bfr[4];
            wmma::load_matrix_sync(af[0], As + (w * 32 + 0) * LDA + k, LDA);
            wmma::load_matrix_sync(af[1], As + (w * 32 + 16) * LDA + k, LDA);
#pragma unroll
            for (int j = 0; j < 4; j++)
                wmma::load_matrix_sync(bfr[j], Ws + k * LDW + j * 16, LDW);
#pragma unroll
            for (int i = 0; i < 2; i++)
#pragma unroll
                for (int j = 0; j < 4; j++)
                    wmma::mma_sync(acc[i][j], af[i], bfr[j], acc[i][j]);
        }
        __syncthreads();
#pragma unroll
        for (int i = 0; i < 2; i++)
#pragma unroll
            for (int j = 0; j < 4; j++)
                wmma::store_matrix_sync(St + (w * 32 + i * 16) * LDS_ + j * 16,
                                        acc[i][j], LDS_, wmma::mem_row_major);
        __syncthreads();

        const int lane = t & 7;
        const int rsub = t >> 3;
#pragma unroll
        for (int g = 0; g < 8; g++) {
            int r = g * 16 + rsub;
            int gr = row0 + r;
            if (gr >= n) continue;
            const float* sp = St + r * LDS_ + lane * 8;
            float* outp = (float*)outv + (size_t)gr * C + bn0 + lane * 8;
            const float* bp = bias + bn0 + lane * 8;
            float ov[8];
#pragma unroll
            for (int q = 0; q < 8; q++)
                ov[q] = 1.f / (1.f + __expf(-(sp[q] + bp[q])));
            *(float4*)outp = *(float4*)ov;
            *(float4*)(outp + 4) = *(float4*)(ov + 4);
        }
    }
}

// ---------------- int8 dequant helper: 8 int8 -> 4 scaled half2 -------------
__device__ __forceinline__ void dq8(uint2 d, __half2 s2, __half2 negoff,
                                    __half2* out4) {
    unsigned int w0 = d.x ^ 0x80808080u;
    unsigned int w1 = d.y ^ 0x80808080u;
    unsigned int p0 = __byte_perm(w0, 0x64, 0x4140);
    unsigned int p1 = __byte_perm(w0, 0x64, 0x4342);
    unsigned int p2 = __byte_perm(w1, 0x64, 0x4140);
    unsigned int p3 = __byte_perm(w1, 0x64, 0x4342);
    out4[0] = __hfma2(*(__half2*)&p0, s2, negoff);
    out4[1] = __hfma2(*(__half2*)&p1, s2, negoff);
    out4[2] = __hfma2(*(__half2*)&p2, s2, negoff);
    out4[3] = __hfma2(*(__half2*)&p3, s2, negoff);
}

// ---------------- aggregation (int8 msgs + inline chunk scales) -------------
template <int D, bool RELU>
__global__ __launch_bounds__(256) void agg_kernel(
    const unsigned char* __restrict__ qs, const float* __restrict__ bias,
    __half* __restrict__ out, int n) {
    constexpr int SB = D + 32;
    constexpr int LPN = D / 8;
    int idx = blockIdx.x * blockDim.x + threadIdx.x;
    int v = idx / LPN;
    int lane = idx % LPN;
    if (v >= n) return;
    int c = lane * 8;
    const __half2 cneg1152 = __float2half2_rn(-1152.f);

    float acc[8];
    {
        const unsigned char* row = qs + (size_t)v * SB;
        uint2 d = *(const uint2*)(row + c);
        __half s = *(const __half*)(row + D + lane * 2);
        __half2 s2 = __half2half2(s);
        __half2 negoff = __hmul2(s2, cneg1152);
        __half2 x[4];
        dq8(d, s2, negoff, x);
#pragma unroll
        for (int q = 0; q < 4; q++) {
            float2 f = __half22float2(x[q]);
            acc[2 * q] = f.x; acc[2 * q + 1] = f.y;
        }
    }
    int e = g_rowptr[v];
    const int end = g_rowptr[v + 1];

    for (; e + 3 < end; e += 4) {
        int u0 = g_col[e],     u1 = g_col[e + 1];
        int u2 = g_col[e + 2], u3 = g_col[e + 3];
        const unsigned char* r0 = qs + (size_t)u0 * SB;
        const unsigned char* r1 = qs + (size_t)u1 * SB;
        const unsigned char* r2 = qs + (size_t)u2 * SB;
        const unsigned char* r3 = qs + (size_t)u3 * SB;
        uint2 d0 = *(const uint2*)(r0 + c);
        uint2 d1 = *(const uint2*)(r1 + c);
        uint2 d2 = *(const uint2*)(r2 + c);
        uint2 d3 = *(const uint2*)(r3 + c);
        __half s0 = *(const __half*)(r0 + D + lane * 2);
        __half s1 = *(const __half*)(r1 + D + lane * 2);
        __half s2h = *(const __half*)(r2 + D + lane * 2);
        __half s3 = *(const __half*)(r3 + D + lane * 2);
        __half2 sa = __half2half2(s0), sb = __half2half2(s1);
        __half2 sc = __half2half2(s2h), sd = __half2half2(s3);
        __half2 x0[4], x1[4], x2[4], x3[4];
        dq8(d0, sa, __hmul2(sa, cneg1152), x0);
        dq8(d1, sb, __hmul2(sb, cneg1152), x1);
        dq8(d2, sc, __hmul2(sc, cneg1152), x2);
        dq8(d3, sd, __hmul2(sd, cneg1152), x3);
#pragma unroll
        for (int q = 0; q < 4; q++) {
            __half2 tq = __hadd2(__hadd2(x0[q], x1[q]), __hadd2(x2[q], x3[q]));
            float2 f = __half22float2(tq);
            acc[2 * q] += f.x;
            acc[2 * q + 1] += f.y;
        }
    }
    for (; e < end; e++) {
        int u = g_col[e];
        const unsigned char* r0 = qs + (size_t)u * SB;
        uint2 d = *(const uint2*)(r0 + c);
        __half s = *(const __half*)(r0 + D + lane * 2);
        __half2 s2 = __half2half2(s);
        __half2 x[4];
        dq8(d, s2, __hmul2(s2, cneg1152), x);
#pragma unroll
        for (int q = 0; q < 4; q++) {
            float2 f = __half22float2(x[q]);
            acc[2 * q] += f.x;
            acc[2 * q + 1] += f.y;
        }
    }
    float s = g_dinv[v];
    float4 b0 = *(const float4*)(bias + c);
    float4 b1 = *(const float4*)(bias + c + 4);
    float bb[8] = {b0.x, b0.y, b0.z, b0.w, b1.x, b1.y, b1.z, b1.w};
    uint4 pk;
    __half2* hv = (__half2*)&pk;
#pragma unroll
    for (int q = 0; q < 4; q++) {
        float r0 = s * acc[2 * q] + bb[2 * q];
        float r1 = s * acc[2 * q + 1] + bb[2 * q + 1];
        if (RELU) { r0 = fmaxf(r0, 0.f); r1 = fmaxf(r1, 0.f); }
        hv[q] = __floats2half2_rn(r0, r1);
    }
    *(uint4*)(out + (size_t)v * D + c) = pk;
}

// ---------------- host launch ----------------
extern "C" void kernel_launch(void* const* d_in, const int* in_sizes, int n_in,
                              void* d_out, int out_size) {
    const float* x   = (const float*)d_in[0];
    const float* y   = (const float*)d_in[1];
    const int*   ei  = (const int*)d_in[2];
    const float* Wg1 = (const float*)d_in[3];
    const float* bg1 = (const float*)d_in[4];
    const float* Wg2 = (const float*)d_in[5];
    const float* bg2 = (const float*)d_in[6];
    const float* Wl  = (const float*)d_in[7];
    const float* bl  = (const float*)d_in[8];
    const float* Wf  = (const float*)d_in[9];
    const float* bf  = (const float*)d_in[10];
    float* out = (float*)d_out;

    int n = in_sizes[0] / 128;
    int e = in_sizes[2] / 2;
    const int* src = ei;
    const int* dst = ei + e;

    __half *hB, *hH2, *hD, *Wh;
    unsigned char* qbuf;
    cudaGetSymbolAddress((void**)&qbuf, g_q);
    cudaGetSymbolAddress((void**)&hB, g_hB);
    cudaGetSymbolAddress((void**)&hH2, g_hH2);
    cudaGetSymbolAddress((void**)&hD, g_hD);
    cudaGetSymbolAddress((void**)&Wh, g_W);
    const __half* Wg1h = Wh;
    const __half* Wg2h = Wh + 16384;
    const __half* Wlh  = Wh + 32768;
    const __half* Wfh  = Wh + 73728;

    auto smem0 = [](int K) -> size_t {
        return (size_t)K * (GBN + 8) * 2 + (size_t)GBM * (K + 8) * 2;
    };
    auto smem1 = [](int K) -> size_t {
        size_t WsB = (size_t)K * (GBN + 8) * 2;
        size_t AsB = (size_t)GBM * (K + 8) * 2;
        size_t StB = (size_t)GBM * (GBN + 4) * 4;
        return WsB + (AsB > StB ? AsB : StB);
    };
    size_t sm64 = smem0(64), sm128 = smem0(128), sm192 = smem1(192);

    cudaFuncSetAttribute((const void*)gemm_wmma_kernel<128, 128, 128, 0, float>,
                         cudaFuncAttributeMaxDynamicSharedMemorySize, (int)sm128);
    cudaFuncSetAttribute((const void*)gemm_wmma_kernel<128, 128, 128, 0, __half>,
                         cudaFuncAttributeMaxDynamicSharedMemorySize, (int)sm128);
    cudaFuncSetAttribute((const void*)gemm_wmma_kernel<64, 64, 64, 0, float>,
                         cudaFuncAttributeMaxDynamicSharedMemorySize, (int)sm64);
    cudaFuncSetAttribute((const void*)gemm_wmma_kernel<64, 64, 64, 0, __half>,
                         cudaFuncAttributeMaxDynamicSharedMemorySize, (int)sm64);
    cudaFuncSetAttribute((const void*)gemm_wmma_kernel<192, 64, 128, 1, __half>,
                         cudaFuncAttributeMaxDynamicSharedMemorySize, (int)sm192);

    int nb_n = (n + 255) / 256;
    int nb_e = (e + 255) / 256;
    int nb_scan = (n + 1023) / 1024;

    init_kernel<<<nb_n, 256>>>(Wg1, Wg2, Wl, Wf, n);
    count_edges_kernel<<<nb_e, 256>>>(dst, e);
    scan1_kernel<<<nb_scan, 1024>>>(n);
    scan2_kernel<<<1, 128>>>(nb_scan);
    scan3_kernel<<<(n + 1023) / 1024, 1024>>>(n, nb_scan);
    scatter_edges_kernel<<<nb_e, 256>>>(src, dst, e);

    int rb = (n + GBM - 1) / GBM;
    dim3 g128(rb, 2);
    dim3 g64(rb, 1);
    int agg128_blocks = (int)(((size_t)n * 16 + 255) / 256);
    int agg64_blocks  = (int)(((size_t)n * 8 + 255) / 256);

    // feature branch
    gemm_wmma_kernel<128, 128, 128, 0, float><<<g128, 128, sm128>>>(
        x, nullptr, Wg1h, nullptr, qbuf, n);
    agg_kernel<128, true><<<agg128_blocks, 256>>>(qbuf, bg1, hB, n);
    gemm_wmma_kernel<128, 128, 128, 0, __half><<<g128, 128, sm128>>>(
        hB, nullptr, Wg2h, nullptr, qbuf, n);
    agg_kernel<128, false><<<agg128_blocks, 256>>>(qbuf, bg2, hH2, n);

    // label branch
    gemm_wmma_kernel<64, 64, 64, 0, float><<<g64, 128, sm64>>>(
        y, nullptr, Wlh, nullptr, qbuf, n);
    agg_kernel<64, true><<<agg64_blocks, 256>>>(qbuf, bl, hD, n);
    for (int j = 1; j < 10; j++) {
        gemm_wmma_kernel<64, 64, 64, 0, __half><<<g64, 128, sm64>>>(
            hD, nullptr, Wlh + (size_t)j * 64 * 64, nullptr, qbuf, n);
        if (j < 9)
            agg_kernel<64, true><<<agg64_blocks, 256>>>(
                qbuf, bl + (size_t)j * 64, hD, n);
        else
            agg_kernel<64, false><<<agg64_blocks, 256>>>(
                qbuf, bl + (size_t)j * 64, hD, n);
    }

    // final fused layer: sigmoid(concat(h2, xl) @ Wf + bf)
    gemm_wmma_kernel<192, 64, 128, 1, __half><<<g64, 128, sm192>>>(
        hH2, hD, Wfh, bf, out, n);
}

// round 16
// speedup vs baseline: 1.1337x; 1.1337x over previous
#include <cuda_runtime.h>
#include <cuda_fp16.h>
#include <mma.h>
#include <math.h>

using namespace nvcuda;

#define NMAX 100000
#define EMAX 1600000
#define NPAD (NMAX + 128)

// ---------------- device scratch ----------------
__device__ float  g_dinv[NMAX];
__device__ int    g_cnt[NMAX];
__device__ int    g_fill[NMAX];
__device__ int    g_rowptr[NMAX + 1];
__device__ int    g_bsum[256];
__device__ int    g_col[EMAX];
__device__ __half g_hA[(size_t)NPAD * 128];
__device__ __half g_hB[(size_t)NPAD * 128];
__device__ __half g_hH2[(size_t)NPAD * 128];
__device__ __half g_hD[(size_t)NPAD * 64];
__device__ __half g_W[86016];

// ---------------- init: zero counts + convert weights --------------
__global__ void init_kernel(const float* __restrict__ Wg1,
                            const float* __restrict__ Wg2,
                            const float* __restrict__ Wl,
                            const float* __restrict__ Wf, int n) {
    int i = blockIdx.x * blockDim.x + threadIdx.x;
    if (i < n) { g_cnt[i] = 0; g_fill[i] = 0; }
    if (i < 21504) {
        int base = i * 4;
        const float* src;
        int off;
        if (base < 16384)      { src = Wg1; off = base; }
        else if (base < 32768) { src = Wg2; off = base - 16384; }
        else if (base < 73728) { src = Wl;  off = base - 32768; }
        else                   { src = Wf;  off = base - 73728; }
        float4 v = *(const float4*)(src + off);
        uint2 pk;
        __half2* h = (__half2*)&pk;
        h[0] = __floats2half2_rn(v.x, v.y);
        h[1] = __floats2half2_rn(v.z, v.w);
        *(uint2*)&g_W[base] = pk;
    }
}

// ---------------- CSR build (vectorized) ----------------
__global__ void count_edges_kernel(const int* __restrict__ dst, int e) {
    int i = blockIdx.x * blockDim.x + threadIdx.x;
    int b = i * 4;
    if (b + 3 < e) {
        int4 d = *(const int4*)(dst + b);
        atomicAdd(&g_cnt[d.x], 1);
        atomicAdd(&g_cnt[d.y], 1);
        atomicAdd(&g_cnt[d.z], 1);
        atomicAdd(&g_cnt[d.w], 1);
    } else {
        for (int k = b; k < e; k++) atomicAdd(&g_cnt[dst[k]], 1);
    }
}

__global__ void scan1_kernel(int n) {
    __shared__ int s[1024];
    int tid = threadIdx.x;
    int i = blockIdx.x * 1024 + tid;
    int v = (i < n) ? g_cnt[i] : 0;
    s[tid] = v;
    __syncthreads();
    for (int off = 1; off < 1024; off <<= 1) {
        int t2 = (tid >= off) ? s[tid - off] : 0;
        __syncthreads();
        s[tid] += t2;
        __syncthreads();
    }
    if (i < n) {
        g_rowptr[i] = s[tid] - v;
        g_dinv[i] = rsqrtf((float)(v + 1));
    }
    if (tid == 1023) g_bsum[blockIdx.x] = s[1023];
}

__global__ void scan2_kernel(int nb) {
    __shared__ int s[128];
    int tid = threadIdx.x;
    int v = (tid < nb) ? g_bsum[tid] : 0;
    s[tid] = v;
    __syncthreads();
    for (int off = 1; off < 128; off <<= 1) {
        int t2 = (tid >= off) ? s[tid - off] : 0;
        __syncthreads();
        s[tid] += t2;
        __syncthreads();
    }
    if (tid < nb) g_bsum[tid] = s[tid] - v;
    if (tid == 127) g_bsum[nb] = s[127];
}

__global__ void scan3_kernel(int n, int nb) {
    int i = blockIdx.x * blockDim.x + threadIdx.x;
    if (i < n) g_rowptr[i] += g_bsum[i >> 10];
    if (i == 0) g_rowptr[n] = g_bsum[nb];
}

__global__ void scatter_edges_kernel(const int* __restrict__ src,
                                     const int* __restrict__ dst, int e) {
    int i = blockIdx.x * blockDim.x + threadIdx.x;
    int b = i * 2;
    if (b + 1 < e) {
        int2 sv = *(const int2*)(src + b);
        int2 dv = *(const int2*)(dst + b);
        int p0 = g_rowptr[dv.x] + atomicAdd(&g_fill[dv.x], 1);
        g_col[p0] = sv.x;
        int p1 = g_rowptr[dv.y] + atomicAdd(&g_fill[dv.y], 1);
        g_col[p1] = sv.y;
    } else if (b < e) {
        int d = dst[b];
        int p = g_rowptr[d] + atomicAdd(&g_fill[d], 1);
        g_col[p] = src[b];
    }
}

// ---------------- wmma GEMM ----------------
// EPI 0: half accumulators, direct global store (padded output rows)
// EPI 1: fp32 accum + smem staging + sigmoid, fp32 out (row-guarded)
#define GBM 128
#define GBN 64

template <int K, int C, int K1, int EPI, typename TA>
__global__ __launch_bounds__(128) void gemm_wmma_kernel(
    const TA* __restrict__ A1, const __half* __restrict__ A2,
    const __half* __restrict__ Wh, const float* __restrict__ bias,
    void* __restrict__ outv, int n) {
    constexpr int LDW = GBN + 8;
    constexpr int LDA = K + 8;
    constexpr int LDS_ = GBN + 4;
    extern __shared__ char smraw[];
    __half* Ws = (__half*)smraw;
    __half* As = (__half*)(smraw + (size_t)K * LDW * 2);
    float*  St = (float*)(smraw + (size_t)K * LDW * 2);

    const int t = threadIdx.x;
    const int w = t >> 5;
    const int row0 = blockIdx.x * GBM;
    const int bn0 = blockIdx.y * GBN;

    for (int idx = t; idx < K * GBN / 8; idx += 128) {
        int k = idx / (GBN / 8);
        int j = (idx % (GBN / 8)) * 8;
        *(uint4*)&Ws[k * LDW + j] =
            *(const uint4*)(Wh + (size_t)k * C + bn0 + j);
    }

    constexpr int CPR = K / 8;
#pragma unroll
    for (int it = 0; it < GBM * CPR / 128; it++) {
        int cidx = t + it * 128;
        int r = cidx / CPR;
        int kq = (cidx % CPR) * 8;
        int gr = row0 + r;
        uint4 pk = make_uint4(0, 0, 0, 0);
        if (gr < n) {
            float s = (EPI == 0) ? g_dinv[gr] : 1.0f;
            __half2 s2 = __float2half2_rn(s);
            if (kq < K1) {
                if (sizeof(TA) == 2) {
                    uint4 raw = *(const uint4*)((const __half*)A1 +
                                                (size_t)gr * K1 + kq);
                    __half2* h = (__half2*)&raw;
                    if (EPI == 0) {
#pragma unroll
                        for (int q = 0; q < 4; q++) h[q] = __hmul2(h[q], s2);
                    }
                    pk = raw;
                } else {
                    const float* p = (const float*)A1 + (size_t)gr * K1 + kq;
                    float4 a = *(const float4*)p;
                    float4 b = *(const float4*)(p + 4);
                    __half2* h = (__half2*)&pk;
                    h[0] = __floats2half2_rn(s * a.x, s * a.y);
                    h[1] = __floats2half2_rn(s * a.z, s * a.w);
                    h[2] = __floats2half2_rn(s * b.x, s * b.y);
                    h[3] = __floats2half2_rn(s * b.z, s * b.w);
                }
            } else {
                uint4 raw = *(const uint4*)(A2 + (size_t)gr * (K - K1) +
                                            (kq - K1));
                __half2* h = (__half2*)&raw;
                if (EPI == 0) {
#pragma unroll
                    for (int q = 0; q < 4; q++) h[q] = __hmul2(h[q], s2);
                }
                pk = raw;
            }
        }
        *(uint4*)&As[r * LDA + kq] = pk;
    }
    __syncthreads();

    if (EPI == 0) {
        wmma::fragment<wmma::accumulator, 16, 16, 16, __half> acc[2][4];
#pragma unroll
        for (int i = 0; i < 2; i++)
#pragma unroll
            for (int j = 0; j < 4; j++)
                wmma::fill_fragment(acc[i][j], __float2half(0.f));
        for (int k = 0; k < K; k += 16) {
            wmma::fragment<wmma::matrix_a, 16, 16, 16, __half, wmma::row_major> af[2];
            wmma::fragment<wmma::matrix_b, 16, 16, 16, __half, wmma::row_major> bfr[4];
            wmma::load_matrix_sync(af[0], As + (w * 32 + 0) * LDA + k, LDA);
            wmma::load_matrix_sync(af[1], As + (w * 32 + 16) * LDA + k, LDA);
#pragma unroll
            for (int j = 0; j < 4; j++)
                wmma::load_matrix_sync(bfr[j], Ws + k * LDW + j * 16, LDW);
#pragma unroll
            for (int i = 0; i < 2; i++)
#pragma unroll
                for (int j = 0; j < 4; j++)
                    wmma::mma_sync(acc[i][j], af[i], bfr[j], acc[i][j]);
        }
        __half* outp = (__half*)outv;
#pragma unroll
        for (int i = 0; i < 2; i++)
#pragma unroll
            for (int j = 0; j < 4; j++)
                wmma::store_matrix_sync(
                    outp + (size_t)(row0 + w * 32 + i * 16) * C + bn0 + j * 16,
                    acc[i][j], C, wmma::mem_row_major);
    } else {
        wmma::fragment<wmma::accumulator, 16, 16, 16, float> acc[2][4];
#pragma unroll
        for (int i = 0; i < 2; i++)
#pragma unroll
            for (int j = 0; j < 4; j++) wmma::fill_fragment(acc[i][j], 0.f);
        for (int k = 0; k < K; k += 16) {
            wmma::fragment<wmma::matrix_a, 16, 16, 16, __half, wmma::row_major> af[2];
            wmma::fragment<wmma::matrix_b, 16, 16, 16, __half, wmma::row_major> bfr[4];
            wmma::load_matrix_sync(af[0], As + (w * 32 + 0) * LDA + k, LDA);
            wmma::load_matrix_sync(af[1], As + (w * 32 + 16) * LDA + k, LDA);
#pragma unroll
            for (int j = 0; j < 4; j++)
                wmma::load_matrix_sync(bfr[j], Ws + k * LDW + j * 16, LDW);
#pragma unroll
            for (int i = 0; i < 2; i++)
#pragma unroll
                for (int j = 0; j < 4; j++)
                    wmma::mma_sync(acc[i][j], af[i], bfr[j], acc[i][j]);
        }
        __syncthreads();
#pragma unroll
        for (int i = 0; i < 2; i++)
#pragma unroll
            for (int j = 0; j < 4; j++)
                wmma::store_matrix_sync(St + (w * 32 + i * 16) * LDS_ + j * 16,
                                        acc[i][j], LDS_, wmma::mem_row_major);
        __syncthreads();

        const int lane = t & 7;
        const int rsub = t >> 3;
#pragma unroll
        for (int g = 0; g < 8; g++) {
            int r = g * 16 + rsub;
            int gr = row0 + r;
            if (gr >= n) continue;
            const float* sp = St + r * LDS_ + lane * 8;
            float* outp = (float*)outv + (size_t)gr * C + bn0 + lane * 8;
            const float* bp = bias + bn0 + lane * 8;
            float ov[8];
#pragma unroll
            for (int q = 0; q < 8; q++)
                ov[q] = 1.f / (1.f + __expf(-(sp[q] + bp[q])));
            *(float4*)outp = *(float4*)ov;
            *(float4*)(outp + 4) = *(float4*)(ov + 4);
        }
    }
}

// ---------------- aggregation: rowptr broadcast + 8-wide unroll -------------
template <int D, bool RELU>
__global__ __launch_bounds__(256) void agg_kernel(
    const __half* __restrict__ hs, const float* __restrict__ bias,
    __half* __restrict__ out, int n) {
    constexpr int LPN = D / 8;  // lanes per node (8 or 16), divides 32
    int idx = blockIdx.x * blockDim.x + threadIdx.x;
    int v = idx / LPN;
    int lane = idx % LPN;
    bool valid = v < n;
    if (!valid) v = n - 1;  // clamp: keep warp converged for shfl
    int c = lane * 8;
    const uint4* base = (const uint4*)hs;
    size_t selfidx = ((size_t)v * D + c) >> 3;

    // rowptr broadcast: lanes 0/1 of each group load, shfl to the rest
    const int wl = threadIdx.x & 31;
    const int gbase = wl & ~(LPN - 1);
    int ld = 0;
    if ((wl & (LPN - 1)) == 0) ld = g_rowptr[v];
    else if ((wl & (LPN - 1)) == 1) ld = g_rowptr[v + 1];
    int e = __shfl_sync(0xffffffffu, ld, gbase);
    const int end = __shfl_sync(0xffffffffu, ld, gbase + 1);

    float acc[8];
    {
        uint4 sv = base[selfidx];
        const __half2* h = (const __half2*)&sv;
#pragma unroll
        for (int q = 0; q < 4; q++) {
            float2 f = __half22float2(h[q]);
            acc[2 * q] = f.x; acc[2 * q + 1] = f.y;
        }
    }

    for (; e + 7 < end; e += 8) {
        int u0 = g_col[e],     u1 = g_col[e + 1];
        int u2 = g_col[e + 2], u3 = g_col[e + 3];
        int u4 = g_col[e + 4], u5 = g_col[e + 5];
        int u6 = g_col[e + 6], u7 = g_col[e + 7];
        uint4 m0 = base[((size_t)u0 * D + c) >> 3];
        uint4 m1 = base[((size_t)u1 * D + c) >> 3];
        uint4 m2 = base[((size_t)u2 * D + c) >> 3];
        uint4 m3 = base[((size_t)u3 * D + c) >> 3];
        uint4 m4 = base[((size_t)u4 * D + c) >> 3];
        uint4 m5 = base[((size_t)u5 * D + c) >> 3];
        uint4 m6 = base[((size_t)u6 * D + c) >> 3];
        uint4 m7 = base[((size_t)u7 * D + c) >> 3];
        const __half2* h0 = (const __half2*)&m0;
        const __half2* h1 = (const __half2*)&m1;
        const __half2* h2 = (const __half2*)&m2;
        const __half2* h3 = (const __half2*)&m3;
        const __half2* h4 = (const __half2*)&m4;
        const __half2* h5 = (const __half2*)&m5;
        const __half2* h6 = (const __half2*)&m6;
        const __half2* h7 = (const __half2*)&m7;
#pragma unroll
        for (int q = 0; q < 4; q++) {
            __half2 ta = __hadd2(__hadd2(h0[q], h1[q]), __hadd2(h2[q], h3[q]));
            __half2 tb = __hadd2(__hadd2(h4[q], h5[q]), __hadd2(h6[q], h7[q]));
            float2 fa = __half22float2(ta);
            float2 fb = __half22float2(tb);
            acc[2 * q] += fa.x + fb.x;
            acc[2 * q + 1] += fa.y + fb.y;
        }
    }
    for (; e + 3 < end; e += 4) {
        int u0 = g_col[e],     u1 = g_col[e + 1];
        int u2 = g_col[e + 2], u3 = g_col[e + 3];
        uint4 m0 = base[((size_t)u0 * D + c) >> 3];
        uint4 m1 = base[((size_t)u1 * D + c) >> 3];
        uint4 m2 = base[((size_t)u2 * D + c) >> 3];
        uint4 m3 = base[((size_t)u3 * D + c) >> 3];
        const __half2* h0 = (const __half2*)&m0;
        const __half2* h1 = (const __half2*)&m1;
        const __half2* h2 = (const __half2*)&m2;
        const __half2* h3 = (const __half2*)&m3;
#pragma unroll
        for (int q = 0; q < 4; q++) {
            __half2 tq = __hadd2(__hadd2(h0[q], h1[q]), __hadd2(h2[q], h3[q]));
            float2 f = __half22float2(tq);
            acc[2 * q] += f.x;
            acc[2 * q + 1] += f.y;
        }
    }
    for (; e < end; e++) {
        int u = g_col[e];
        uint4 m = base[((size_t)u * D + c) >> 3];
        const __half2* h = (const __half2*)&m;
#pragma unroll
        for (int q = 0; q < 4; q++) {
            float2 f = __half22float2(h[q]);
            acc[2 * q] += f.x;
            acc[2 * q + 1] += f.y;
        }
    }
    if (!valid) return;
    float s = g_dinv[v];
    float4 b0 = *(const float4*)(bias + c);
    float4 b1 = *(const float4*)(bias + c + 4);
    float bb[8] = {b0.x, b0.y, b0.z, b0.w, b1.x, b1.y, b1.z, b1.w};
    uint4 pk;
    __half2* hv = (__half2*)&pk;
#pragma unroll
    for (int q = 0; q < 4; q++) {
        float r0 = s * acc[2 * q] + bb[2 * q];
        float r1 = s * acc[2 * q + 1] + bb[2 * q + 1];
        if (RELU) { r0 = fmaxf(r0, 0.f); r1 = fmaxf(r1, 0.f); }
        hv[q] = __floats2half2_rn(r0, r1);
    }
    ((uint4*)out)[selfidx] = pk;
}

// ---------------- host launch ----------------
extern "C" void kernel_launch(void* const* d_in, const int* in_sizes, int n_in,
                              void* d_out, int out_size) {
    const float* x   = (const float*)d_in[0];
    const float* y   = (const float*)d_in[1];
    const int*   ei  = (const int*)d_in[2];
    const float* Wg1 = (const float*)d_in[3];
    const float* bg1 = (const float*)d_in[4];
    const float* Wg2 = (const float*)d_in[5];
    const float* bg2 = (const float*)d_in[6];
    const float* Wl  = (const float*)d_in[7];
    const float* bl  = (const float*)d_in[8];
    const float* Wf  = (const float*)d_in[9];
    const float* bf  = (const float*)d_in[10];
    float* out = (float*)d_out;

    int n = in_sizes[0] / 128;
    int e = in_sizes[2] / 2;
    const int* src = ei;
    const int* dst = ei + e;

    __half *hA, *hB, *hH2, *hD, *Wh;
    cudaGetSymbolAddress((void**)&hA, g_hA);
    cudaGetSymbolAddress((void**)&hB, g_hB);
    cudaGetSymbolAddress((void**)&hH2, g_hH2);
    cudaGetSymbolAddress((void**)&hD, g_hD);
    cudaGetSymbolAddress((void**)&Wh, g_W);
    const __half* Wg1h = Wh;
    const __half* Wg2h = Wh + 16384;
    const __half* Wlh  = Wh + 32768;
    const __half* Wfh  = Wh + 73728;

    auto smem0 = [](int K) -> size_t {
        return (size_t)K * (GBN + 8) * 2 + (size_t)GBM * (K + 8) * 2;
    };
    auto smem1 = [](int K) -> size_t {
        size_t WsB = (size_t)K * (GBN + 8) * 2;
        size_t AsB = (size_t)GBM * (K + 8) * 2;
        size_t StB = (size_t)GBM * (GBN + 4) * 4;
        return WsB + (AsB > StB ? AsB : StB);
    };
    size_t sm64 = smem0(64), sm128 = smem0(128), sm192 = smem1(192);

    cudaFuncSetAttribute((const void*)gemm_wmma_kernel<128, 128, 128, 0, float>,
                         cudaFuncAttributeMaxDynamicSharedMemorySize, (int)sm128);
    cudaFuncSetAttribute((const void*)gemm_wmma_kernel<128, 128, 128, 0, __half>,
                         cudaFuncAttributeMaxDynamicSharedMemorySize, (int)sm128);
    cudaFuncSetAttribute((const void*)gemm_wmma_kernel<64, 64, 64, 0, float>,
                         cudaFuncAttributeMaxDynamicSharedMemorySize, (int)sm64);
    cudaFuncSetAttribute((const void*)gemm_wmma_kernel<64, 64, 64, 0, __half>,
                         cudaFuncAttributeMaxDynamicSharedMemorySize, (int)sm64);
    cudaFuncSetAttribute((const void*)gemm_wmma_kernel<192, 64, 128, 1, __half>,
                         cudaFuncAttributeMaxDynamicSharedMemorySize, (int)sm192);

    int nb_n = (n + 255) / 256;
    int nb_e4 = (e / 4 + 256) / 256;
    int nb_e2 = (e / 2 + 256) / 256;
    int nb_scan = (n + 1023) / 1024;

    init_kernel<<<nb_n, 256>>>(Wg1, Wg2, Wl, Wf, n);
    count_edges_kernel<<<nb_e4, 256>>>(dst, e);
    scan1_kernel<<<nb_scan, 1024>>>(n);
    scan2_kernel<<<1, 128>>>(nb_scan);
    scan3_kernel<<<(n + 1023) / 1024, 1024>>>(n, nb_scan);
    scatter_edges_kernel<<<nb_e2, 256>>>(src, dst, e);

    int rb = (n + GBM - 1) / GBM;
    dim3 g128(rb, 2);
    dim3 g64(rb, 1);
    int agg128_blocks = (int)(((size_t)n * 16 + 255) / 256);
    int agg64_blocks  = (int)(((size_t)n * 8 + 255) / 256);

    // feature branch
    gemm_wmma_kernel<128, 128, 128, 0, float><<<g128, 128, sm128>>>(
        x, nullptr, Wg1h, nullptr, hA, n);
    agg_kernel<128, true><<<agg128_blocks, 256>>>(hA, bg1, hB, n);
    gemm_wmma_kernel<128, 128, 128, 0, __half><<<g128, 128, sm128>>>(
        hB, nullptr, Wg2h, nullptr, hA, n);
    agg_kernel<128, false><<<agg128_blocks, 256>>>(hA, bg2, hH2, n);

    // label branch
    gemm_wmma_kernel<64, 64, 64, 0, float><<<g64, 128, sm64>>>(
        y, nullptr, Wlh, nullptr, hA, n);
    agg_kernel<64, true><<<agg64_blocks, 256>>>(hA, bl, hD, n);
    for (int j = 1; j < 10; j++) {
        gemm_wmma_kernel<64, 64, 64, 0, __half><<<g64, 128, sm64>>>(
            hD, nullptr, Wlh + (size_t)j * 64 * 64, nullptr, hA, n);
        if (j < 9)
            agg_kernel<64, true><<<agg64_blocks, 256>>>(
                hA, bl + (size_t)j * 64, hD, n);
        else
            agg_kernel<64, false><<<agg64_blocks, 256>>>(
                hA, bl + (size_t)j * 64, hD, n);
    }

    // final fused layer: sigmoid(concat(h2, xl) @ Wf + bf)
    gemm_wmma_kernel<192, 64, 128, 1, __half><<<g64, 128, sm192>>>(
        hH2, hD, Wfh, bf, out, n);
}

// round 17
// speedup vs baseline: 1.1382x; 1.0039x over previous
#include <cuda_runtime.h>
#include <cuda_fp16.h>
#include <mma.h>
#include <math.h>

using namespace nvcuda;

#define NMAX 100000
#define EMAX 1600000
#define NPAD (NMAX + 128)

// ---------------- device scratch ----------------
__device__ float  g_dinv[NMAX];
__device__ int    g_cnt[NMAX];
__device__ int    g_fill[NMAX];
__device__ int    g_rowptr[NMAX + 1];
__device__ int    g_bsum[256];
__device__ int    g_col[EMAX];
__device__ __half g_hA[(size_t)NPAD * 128];
__device__ __half g_hB[(size_t)NPAD * 128];
__device__ __half g_hH2[(size_t)NPAD * 128];
__device__ __half g_hD[(size_t)NPAD * 64];
__device__ __half g_W[86016];

// ---------------- init: zero counts + convert weights --------------
__global__ void init_kernel(const float* __restrict__ Wg1,
                            const float* __restrict__ Wg2,
                            const float* __restrict__ Wl,
                            const float* __restrict__ Wf, int n) {
    int i = blockIdx.x * blockDim.x + threadIdx.x;
    if (i < n) { g_cnt[i] = 0; g_fill[i] = 0; }
    if (i < 21504) {
        int base = i * 4;
        const float* src;
        int off;
        if (base < 16384)      { src = Wg1; off = base; }
        else if (base < 32768) { src = Wg2; off = base - 16384; }
        else if (base < 73728) { src = Wl;  off = base - 32768; }
        else                   { src = Wf;  off = base - 73728; }
        float4 v = *(const float4*)(src + off);
        uint2 pk;
        __half2* h = (__half2*)&pk;
        h[0] = __floats2half2_rn(v.x, v.y);
        h[1] = __floats2half2_rn(v.z, v.w);
        *(uint2*)&g_W[base] = pk;
    }
}

// ---------------- CSR build (vectorized) ----------------
__global__ void count_edges_kernel(const int* __restrict__ dst, int e) {
    int i = blockIdx.x * blockDim.x + threadIdx.x;
    int b = i * 4;
    if (b + 3 < e) {
        int4 d = *(const int4*)(dst + b);
        atomicAdd(&g_cnt[d.x], 1);
        atomicAdd(&g_cnt[d.y], 1);
        atomicAdd(&g_cnt[d.z], 1);
        atomicAdd(&g_cnt[d.w], 1);
    } else {
        for (int k = b; k < e; k++) atomicAdd(&g_cnt[dst[k]], 1);
    }
}

__global__ void scan1_kernel(int n) {
    __shared__ int s[1024];
    int tid = threadIdx.x;
    int i = blockIdx.x * 1024 + tid;
    int v = (i < n) ? g_cnt[i] : 0;
    s[tid] = v;
    __syncthreads();
    for (int off = 1; off < 1024; off <<= 1) {
        int t2 = (tid >= off) ? s[tid - off] : 0;
        __syncthreads();
        s[tid] += t2;
        __syncthreads();
    }
    if (i < n) {
        g_rowptr[i] = s[tid] - v;
        g_dinv[i] = rsqrtf((float)(v + 1));
    }
    if (tid == 1023) g_bsum[blockIdx.x] = s[1023];
}

__global__ void scan2_kernel(int nb) {
    __shared__ int s[128];
    int tid = threadIdx.x;
    int v = (tid < nb) ? g_bsum[tid] : 0;
    s[tid] = v;
    __syncthreads();
    for (int off = 1; off < 128; off <<= 1) {
        int t2 = (tid >= off) ? s[tid - off] : 0;
        __syncthreads();
        s[tid] += t2;
        __syncthreads();
    }
    if (tid < nb) g_bsum[tid] = s[tid] - v;
    if (tid == 127) g_bsum[nb] = s[127];
}

__global__ void scan3_kernel(int n, int nb) {
    int i = blockIdx.x * blockDim.x + threadIdx.x;
    if (i < n) g_rowptr[i] += g_bsum[i >> 10];
    if (i == 0) g_rowptr[n] = g_bsum[nb];
}

__global__ void scatter_edges_kernel(const int* __restrict__ src,
                                     const int* __restrict__ dst, int e) {
    int i = blockIdx.x * blockDim.x + threadIdx.x;
    int b = i * 2;
    if (b + 1 < e) {
        int2 sv = *(const int2*)(src + b);
        int2 dv = *(const int2*)(dst + b);
        int p0 = g_rowptr[dv.x] + atomicAdd(&g_fill[dv.x], 1);
        g_col[p0] = sv.x;
        int p1 = g_rowptr[dv.y] + atomicAdd(&g_fill[dv.y], 1);
        g_col[p1] = sv.y;
    } else if (b < e) {
        int d = dst[b];
        int p = g_rowptr[d] + atomicAdd(&g_fill[d], 1);
        g_col[p] = src[b];
    }
}

// ---------------- wmma GEMM ----------------
// EPI 0: half accumulators, direct global store (padded output rows)
// EPI 1: fp32 accum + smem staging + sigmoid, fp32 out (row-guarded)
#define GBM 128
#define GBN 64

template <int K, int C, int K1, int EPI, typename TA>
__global__ __launch_bounds__(128) void gemm_wmma_kernel(
    const TA* __restrict__ A1, const __half* __restrict__ A2,
    const __half* __restrict__ Wh, const float* __restrict__ bias,
    void* __restrict__ outv, int n) {
    constexpr int LDW = GBN + 8;
    constexpr int LDA = K + 8;
    constexpr int LDS_ = GBN + 4;
    extern __shared__ char smraw[];
    __half* Ws = (__half*)smraw;
    __half* As = (__half*)(smraw + (size_t)K * LDW * 2);
    float*  St = (float*)(smraw + (size_t)K * LDW * 2);

    const int t = threadIdx.x;
    const int w = t >> 5;
    const int row0 = blockIdx.x * GBM;
    const int bn0 = blockIdx.y * GBN;

    for (int idx = t; idx < K * GBN / 8; idx += 128) {
        int k = idx / (GBN / 8);
        int j = (idx % (GBN / 8)) * 8;
        *(uint4*)&Ws[k * LDW + j] =
            *(const uint4*)(Wh + (size_t)k * C + bn0 + j);
    }

    constexpr int CPR = K / 8;
#pragma unroll
    for (int it = 0; it < GBM * CPR / 128; it++) {
        int cidx = t + it * 128;
        int r = cidx / CPR;
        int kq = (cidx % CPR) * 8;
        int gr = row0 + r;
        uint4 pk = make_uint4(0, 0, 0, 0);
        if (gr < n) {
            float s = (EPI == 0) ? g_dinv[gr] : 1.0f;
            __half2 s2 = __float2half2_rn(s);
            if (kq < K1) {
                if (sizeof(TA) == 2) {
                    uint4 raw = *(const uint4*)((const __half*)A1 +
                                                (size_t)gr * K1 + kq);
                    __half2* h = (__half2*)&raw;
                    if (EPI == 0) {
#pragma unroll
                        for (int q = 0; q < 4; q++) h[q] = __hmul2(h[q], s2);
                    }
                    pk = raw;
                } else {
                    const float* p = (const float*)A1 + (size_t)gr * K1 + kq;
                    float4 a = *(const float4*)p;
                    float4 b = *(const float4*)(p + 4);
                    __half2* h = (__half2*)&pk;
                    h[0] = __floats2half2_rn(s * a.x, s * a.y);
                    h[1] = __floats2half2_rn(s * a.z, s * a.w);
                    h[2] = __floats2half2_rn(s * b.x, s * b.y);
                    h[3] = __floats2half2_rn(s * b.z, s * b.w);
                }
            } else {
                uint4 raw = *(const uint4*)(A2 + (size_t)gr * (K - K1) +
                                            (kq - K1));
                __half2* h = (__half2*)&raw;
                if (EPI == 0) {
#pragma unroll
                    for (int q = 0; q < 4; q++) h[q] = __hmul2(h[q], s2);
                }
                pk = raw;
            }
        }
        *(uint4*)&As[r * LDA + kq] = pk;
    }
    __syncthreads();

    if (EPI == 0) {
        wmma::fragment<wmma::accumulator, 16, 16, 16, __half> acc[2][4];
#pragma unroll
        for (int i = 0; i < 2; i++)
#pragma unroll
            for (int j = 0; j < 4; j++)
                wmma::fill_fragment(acc[i][j], __float2half(0.f));
        for (int k = 0; k < K; k += 16) {
            wmma::fragment<wmma::matrix_a, 16, 16, 16, __half, wmma::row_major> af[2];
            wmma::fragment<wmma::matrix_b, 16, 16, 16, __half, wmma::row_major> bfr[4];
            wmma::load_matrix_sync(af[0], As + (w * 32 + 0) * LDA + k, LDA);
            wmma::load_matrix_sync(af[1], As + (w * 32 + 16) * LDA + k, LDA);
#pragma unroll
            for (int j = 0; j < 4; j++)
                wmma::load_matrix_sync(bfr[j], Ws + k * LDW + j * 16, LDW);
#pragma unroll
            for (int i = 0; i < 2; i++)
#pragma unroll
                for (int j = 0; j < 4; j++)
                    wmma::mma_sync(acc[i][j], af[i], bfr[j], acc[i][j]);
        }
        __half* outp = (__half*)outv;
#pragma unroll
        for (int i = 0; i < 2; i++)
#pragma unroll
            for (int j = 0; j < 4; j++)
                wmma::store_matrix_sync(
                    outp + (size_t)(row0 + w * 32 + i * 16) * C + bn0 + j * 16,
                    acc[i][j], C, wmma::mem_row_major);
    } else {
        wmma::fragment<wmma::accumulator, 16, 16, 16, float> acc[2][4];
#pragma unroll
        for (int i = 0; i < 2; i++)
#pragma unroll
            for (int j = 0; j < 4; j++) wmma::fill_fragment(acc[i][j], 0.f);
        for (int k = 0; k < K; k += 16) {
            wmma::fragment<wmma::matrix_a, 16, 16, 16, __half, wmma::row_major> af[2];
            wmma::fragment<wmma::matrix_b, 16, 16, 16, __half, wmma::row_major> bfr[4];
            wmma::load_matrix_sync(af[0], As + (w * 32 + 0) * LDA + k, LDA);
            wmma::load_matrix_sync(af[1], As + (w * 32 + 16) * LDA + k, LDA);
#pragma unroll
            for (int j = 0; j < 4; j++)
                wmma::load_matrix_sync(bfr[j], Ws + k * LDW + j * 16, LDW);
#pragma unroll
            for (int i = 0; i < 2; i++)
#pragma unroll
                for (int j = 0; j < 4; j++)
                    wmma::mma_sync(acc[i][j], af[i], bfr[j], acc[i][j]);
        }
        __syncthreads();
#pragma unroll
        for (int i = 0; i < 2; i++)
#pragma unroll
            for (int j = 0; j < 4; j++)
                wmma::store_matrix_sync(St + (w * 32 + i * 16) * LDS_ + j * 16,
                                        acc[i][j], LDS_, wmma::mem_row_major);
        __syncthreads();

        const int lane = t & 7;
        const int rsub = t >> 3;
#pragma unroll
        for (int g = 0; g < 8; g++) {
            int r = g * 16 + rsub;
            int gr = row0 + r;
            if (gr >= n) continue;
            const float* sp = St + r * LDS_ + lane * 8;
            float* outp = (float*)outv + (size_t)gr * C + bn0 + lane * 8;
            const float* bp = bias + bn0 + lane * 8;
            float ov[8];
#pragma unroll
            for (int q = 0; q < 8; q++)
                ov[q] = 1.f / (1.f + __expf(-(sp[q] + bp[q])));
            *(float4*)outp = *(float4*)ov;
            *(float4*)(outp + 4) = *(float4*)(ov + 4);
        }
    }
}

// ---------------- aggregation: 8-wide unroll, half2 trees, fp32 sum ----------
template <int D, bool RELU>
__global__ __launch_bounds__(256) void agg_kernel(
    const __half* __restrict__ hs, const float* __restrict__ bias,
    __half* __restrict__ out, int n) {
    constexpr int LPN = D / 8;
    int idx = blockIdx.x * blockDim.x + threadIdx.x;
    int v = idx / LPN;
    int lane = idx % LPN;
    if (v >= n) return;
    int c = lane * 8;
    const uint4* base = (const uint4*)hs;
    size_t selfidx = ((size_t)v * D + c) >> 3;

    float acc[8];
    {
        uint4 sv = base[selfidx];
        const __half2* h = (const __half2*)&sv;
#pragma unroll
        for (int q = 0; q < 4; q++) {
            float2 f = __half22float2(h[q]);
            acc[2 * q] = f.x; acc[2 * q + 1] = f.y;
        }
    }
    int e = g_rowptr[v];
    const int end = g_rowptr[v + 1];

    for (; e + 7 < end; e += 8) {
        int u0 = g_col[e],     u1 = g_col[e + 1];
        int u2 = g_col[e + 2], u3 = g_col[e + 3];
        int u4 = g_col[e + 4], u5 = g_col[e + 5];
        int u6 = g_col[e + 6], u7 = g_col[e + 7];
        uint4 m0 = base[((size_t)u0 * D + c) >> 3];
        uint4 m1 = base[((size_t)u1 * D + c) >> 3];
        uint4 m2 = base[((size_t)u2 * D + c) >> 3];
        uint4 m3 = base[((size_t)u3 * D + c) >> 3];
        uint4 m4 = base[((size_t)u4 * D + c) >> 3];
        uint4 m5 = base[((size_t)u5 * D + c) >> 3];
        uint4 m6 = base[((size_t)u6 * D + c) >> 3];
        uint4 m7 = base[((size_t)u7 * D + c) >> 3];
        const __half2* h0 = (const __half2*)&m0;
        const __half2* h1 = (const __half2*)&m1;
        const __half2* h2 = (const __half2*)&m2;
        const __half2* h3 = (const __half2*)&m3;
        const __half2* h4 = (const __half2*)&m4;
        const __half2* h5 = (const __half2*)&m5;
        const __half2* h6 = (const __half2*)&m6;
        const __half2* h7 = (const __half2*)&m7;
#pragma unroll
        for (int q = 0; q < 4; q++) {
            __half2 ta = __hadd2(__hadd2(h0[q], h1[q]), __hadd2(h2[q], h3[q]));
            __half2 tb = __hadd2(__hadd2(h4[q], h5[q]), __hadd2(h6[q], h7[q]));
            float2 fa = __half22float2(ta);
            float2 fb = __half22float2(tb);
            acc[2 * q] += fa.x + fb.x;
            acc[2 * q + 1] += fa.y + fb.y;
        }
    }
    for (; e + 3 < end; e += 4) {
        int u0 = g_col[e],     u1 = g_col[e + 1];
        int u2 = g_col[e + 2], u3 = g_col[e + 3];
        uint4 m0 = base[((size_t)u0 * D + c) >> 3];
        uint4 m1 = base[((size_t)u1 * D + c) >> 3];
        uint4 m2 = base[((size_t)u2 * D + c) >> 3];
        uint4 m3 = base[((size_t)u3 * D + c) >> 3];
        const __half2* h0 = (const __half2*)&m0;
        const __half2* h1 = (const __half2*)&m1;
        const __half2* h2 = (const __half2*)&m2;
        const __half2* h3 = (const __half2*)&m3;
#pragma unroll
        for (int q = 0; q < 4; q++) {
            __half2 tq = __hadd2(__hadd2(h0[q], h1[q]), __hadd2(h2[q], h3[q]));
            float2 f = __half22float2(tq);
            acc[2 * q] += f.x;
            acc[2 * q + 1] += f.y;
        }
    }
    for (; e < end; e++) {
        int u = g_col[e];
        uint4 m = base[((size_t)u * D + c) >> 3];
        const __half2* h = (const __half2*)&m;
#pragma unroll
        for (int q = 0; q < 4; q++) {
            float2 f = __half22float2(h[q]);
            acc[2 * q] += f.x;
            acc[2 * q + 1] += f.y;
        }
    }
    float s = g_dinv[v];
    float4 b0 = *(const float4*)(bias + c);
    float4 b1 = *(const float4*)(bias + c + 4);
    float bb[8] = {b0.x, b0.y, b0.z, b0.w, b1.x, b1.y, b1.z, b1.w};
    uint4 pk;
    __half2* hv = (__half2*)&pk;
#pragma unroll
    for (int q = 0; q < 4; q++) {
        float r0 = s * acc[2 * q] + bb[2 * q];
        float r1 = s * acc[2 * q + 1] + bb[2 * q + 1];
        if (RELU) { r0 = fmaxf(r0, 0.f); r1 = fmaxf(r1, 0.f); }
        hv[q] = __floats2half2_rn(r0, r1);
    }
    ((uint4*)out)[selfidx] = pk;
}

// ---------------- host launch ----------------
extern "C" void kernel_launch(void* const* d_in, const int* in_sizes, int n_in,
                              void* d_out, int out_size) {
    const float* x   = (const float*)d_in[0];
    const float* y   = (const float*)d_in[1];
    const int*   ei  = (const int*)d_in[2];
    const float* Wg1 = (const float*)d_in[3];
    const float* bg1 = (const float*)d_in[4];
    const float* Wg2 = (const float*)d_in[5];
    const float* bg2 = (const float*)d_in[6];
    const float* Wl  = (const float*)d_in[7];
    const float* bl  = (const float*)d_in[8];
    const float* Wf  = (const float*)d_in[9];
    const float* bf  = (const float*)d_in[10];
    float* out = (float*)d_out;

    int n = in_sizes[0] / 128;
    int e = in_sizes[2] / 2;
    const int* src = ei;
    const int* dst = ei + e;

    __half *hA, *hB, *hH2, *hD, *Wh;
    cudaGetSymbolAddress((void**)&hA, g_hA);
    cudaGetSymbolAddress((void**)&hB, g_hB);
    cudaGetSymbolAddress((void**)&hH2, g_hH2);
    cudaGetSymbolAddress((void**)&hD, g_hD);
    cudaGetSymbolAddress((void**)&Wh, g_W);
    const __half* Wg1h = Wh;
    const __half* Wg2h = Wh + 16384;
    const __half* Wlh  = Wh + 32768;
    const __half* Wfh  = Wh + 73728;

    auto smem0 = [](int K) -> size_t {
        return (size_t)K * (GBN + 8) * 2 + (size_t)GBM * (K + 8) * 2;
    };
    auto smem1 = [](int K) -> size_t {
        size_t WsB = (size_t)K * (GBN + 8) * 2;
        size_t AsB = (size_t)GBM * (K + 8) * 2;
        size_t StB = (size_t)GBM * (GBN + 4) * 4;
        return WsB + (AsB > StB ? AsB : StB);
    };
    size_t sm64 = smem0(64), sm128 = smem0(128), sm192 = smem1(192);

    cudaFuncSetAttribute((const void*)gemm_wmma_kernel<128, 128, 128, 0, float>,
                         cudaFuncAttributeMaxDynamicSharedMemorySize, (int)sm128);
    cudaFuncSetAttribute((const void*)gemm_wmma_kernel<128, 128, 128, 0, __half>,
                         cudaFuncAttributeMaxDynamicSharedMemorySize, (int)sm128);
    cudaFuncSetAttribute((const void*)gemm_wmma_kernel<64, 64, 64, 0, float>,
                         cudaFuncAttributeMaxDynamicSharedMemorySize, (int)sm64);
    cudaFuncSetAttribute((const void*)gemm_wmma_kernel<64, 64, 64, 0, __half>,
                         cudaFuncAttributeMaxDynamicSharedMemorySize, (int)sm64);
    cudaFuncSetAttribute((const void*)gemm_wmma_kernel<192, 64, 128, 1, __half>,
                         cudaFuncAttributeMaxDynamicSharedMemorySize, (int)sm192);

    int nb_n = (n + 255) / 256;
    int nb_e4 = (e / 4 + 256) / 256;
    int nb_e2 = (e / 2 + 256) / 256;
    int nb_scan = (n + 1023) / 1024;

    init_kernel<<<nb_n, 256>>>(Wg1, Wg2, Wl, Wf, n);
    count_edges_kernel<<<nb_e4, 256>>>(dst, e);
    scan1_kernel<<<nb_scan, 1024>>>(n);
    scan2_kernel<<<1, 128>>>(nb_scan);
    scan3_kernel<<<(n + 1023) / 1024, 1024>>>(n, nb_scan);
    scatter_edges_kernel<<<nb_e2, 256>>>(src, dst, e);

    int rb = (n + GBM - 1) / GBM;
    dim3 g128(rb, 2);
    dim3 g64(rb, 1);
    int agg128_blocks = (int)(((size_t)n * 16 + 255) / 256);
    int agg64_blocks  = (int)(((size_t)n * 8 + 255) / 256);

    // feature branch
    gemm_wmma_kernel<128, 128, 128, 0, float><<<g128, 128, sm128>>>(
        x, nullptr, Wg1h, nullptr, hA, n);
    agg_kernel<128, true><<<agg128_blocks, 256>>>(hA, bg1, hB, n);
    gemm_wmma_kernel<128, 128, 128, 0, __half><<<g128, 128, sm128>>>(
        hB, nullptr, Wg2h, nullptr, hA, n);
    agg_kernel<128, false><<<agg128_blocks, 256>>>(hA, bg2, hH2, n);

    // label branch
    gemm_wmma_kernel<64, 64, 64, 0, float><<<g64, 128, sm64>>>(
        y, nullptr, Wlh, nullptr, hA, n);
    agg_kernel<64, true><<<agg64_blocks, 256>>>(hA, bl, hD, n);
    for (int j = 1; j < 10; j++) {
        gemm_wmma_kernel<64, 64, 64, 0, __half><<<g64, 128, sm64>>>(
            hD, nullptr, Wlh + (size_t)j * 64 * 64, nullptr, hA, n);
        if (j < 9)
            agg_kernel<64, true><<<agg64_blocks, 256>>>(
                hA, bl + (size_t)j * 64, hD, n);
        else
            agg_kernel<64, false><<<agg64_blocks, 256>>>(
                hA, bl + (size_t)j * 64, hD, n);
    }

    // final fused layer: sigmoid(concat(h2, xl) @ Wf + bf)
    gemm_wmma_kernel<192, 64, 128, 1, __half><<<g64, 128, sm192>>>(
        hH2, hD, Wfh, bf, out, n);
}